// round 3
// baseline (speedup 1.0000x reference)
#include <cuda_runtime.h>
#include <cuda_bf16.h>

// Problem constants (fixed by the reference)
#define BB 4
#define TT 2048
#define DD 768
#define HH 12
#define HD 64
#define WIN 128
#define QT 64          // queries per attention block
#define NKMAX 192      // max keys per tile = QT + WIN
#define KSTR 65        // padded smem row stride for K/V/Q (bank-conflict free)
#define SSTR 192       // score row stride

// Scratch (device globals — allocation inside kernel_launch is forbidden)
__device__ float g_qkv[(long)BB * TT * 3 * DD];   // [8192, 2304]  ~75.5 MB
__device__ float g_att[(long)BB * TT * DD];       // [8192, 768]   ~25.2 MB

// ---------------------------------------------------------------------------
// Tiled fp32 GEMM: C[M,N] = A[M,K] * B[K,N], all row-major.
// 128x128 block tile, K-tile 16, 256 threads, 8x8 per-thread micro tile.
// M,N,K are multiples of 128/128/16 for all three calls.
// ---------------------------------------------------------------------------
__global__ void __launch_bounds__(256) sgemm128(const float* __restrict__ A,
                                                const float* __restrict__ B,
                                                float* __restrict__ C,
                                                int M, int N, int K) {
    __shared__ float As[16][128];   // transposed A tile: As[k][m]
    __shared__ float Bs[16][128];   // Bs[k][n]

    const int tid = threadIdx.x;
    const int bm  = blockIdx.y * 128;
    const int bn  = blockIdx.x * 128;
    const int tm  = (tid >> 4) * 8;   // 0..120
    const int tn  = (tid & 15) * 8;   // 0..120

    float c[8][8];
#pragma unroll
    for (int i = 0; i < 8; i++)
#pragma unroll
        for (int j = 0; j < 8; j++) c[i][j] = 0.f;

    for (int kt = 0; kt < K; kt += 16) {
        // Load A tile 128x16 (512 float4), store transposed
#pragma unroll
        for (int f = tid; f < 512; f += 256) {
            int row  = f >> 2;          // 0..127
            int col4 = (f & 3) << 2;    // 0,4,8,12
            float4 v = *reinterpret_cast<const float4*>(
                &A[(long)(bm + row) * K + kt + col4]);
            As[col4 + 0][row] = v.x;
            As[col4 + 1][row] = v.y;
            As[col4 + 2][row] = v.z;
            As[col4 + 3][row] = v.w;
        }
        // Load B tile 16x128 (512 float4), coalesced rows
#pragma unroll
        for (int f = tid; f < 512; f += 256) {
            int row  = f >> 5;          // 0..15
            int col4 = (f & 31) << 2;   // 0..124
            float4 v = *reinterpret_cast<const float4*>(
                &B[(long)(kt + row) * N + bn + col4]);
            *reinterpret_cast<float4*>(&Bs[row][col4]) = v;
        }
        __syncthreads();

#pragma unroll
        for (int k = 0; k < 16; k++) {
            float a[8], b[8];
#pragma unroll
            for (int i = 0; i < 8; i++) a[i] = As[k][tm + i];
#pragma unroll
            for (int j = 0; j < 8; j++) b[j] = Bs[k][tn + j];
#pragma unroll
            for (int i = 0; i < 8; i++)
#pragma unroll
                for (int j = 0; j < 8; j++) c[i][j] = fmaf(a[i], b[j], c[i][j]);
        }
        __syncthreads();
    }

#pragma unroll
    for (int i = 0; i < 8; i++) {
        float4 v0 = make_float4(c[i][0], c[i][1], c[i][2], c[i][3]);
        float4 v1 = make_float4(c[i][4], c[i][5], c[i][6], c[i][7]);
        float* crow = &C[(long)(bm + tm + i) * N + bn + tn];
        *reinterpret_cast<float4*>(crow)     = v0;
        *reinterpret_cast<float4*>(crow + 4) = v1;
    }
}

// ---------------------------------------------------------------------------
// Sliding-window attention over the qkv buffer.
// qkv layout: row r = b*T + t, columns [0,768)=Q, [768,1536)=K, [1536,2304)=V,
// each split into H=12 heads of 64.
// One block = (b, h, 64-query tile). Two-pass softmax with scores in smem.
// ---------------------------------------------------------------------------
__global__ void __launch_bounds__(256) attn_kernel(const float* __restrict__ qkv,
                                                   float* __restrict__ att) {
    const int q0 = blockIdx.x * QT;
    const int h  = blockIdx.y;
    const int b  = blockIdx.z;
    const int tid = threadIdx.x;

    extern __shared__ float sm[];
    float* sQ = sm;                        // QT    x KSTR
    float* sK = sQ + QT * KSTR;            // NKMAX x KSTR
    float* sV = sK + NKMAX * KSTR;         // NKMAX x KSTR
    float* sS = sV + NKMAX * KSTR;         // QT    x SSTR

    const int kstart = max(0, q0 - WIN);
    const int kend   = q0 + QT;            // keys <= last query index
    const int nk     = kend - kstart;      // <= 192

    const int hq = h * HD;

    // Load Q tile
    for (int idx = tid; idx < QT * HD; idx += 256) {
        int q = idx >> 6, d = idx & 63;
        sQ[q * KSTR + d] = qkv[(long)(b * TT + q0 + q) * (3 * DD) + hq + d];
    }
    // Load K and V tiles
    for (int idx = tid; idx < nk * HD; idx += 256) {
        int kk = idx >> 6, d = idx & 63;
        long r = (long)(b * TT + kstart + kk) * (3 * DD);
        sK[kk * KSTR + d] = qkv[r + DD + hq + d];
        sV[kk * KSTR + d] = qkv[r + 2 * DD + hq + d];
    }
    __syncthreads();

    // Scores: S[q][kk] = scale * dot(Q[q], K[kk])  (masked outside window)
    const float scale = 0.125f;   // 1/sqrt(64)
    const int total = QT * nk;
    for (int idx = tid; idx < total; idx += 256) {
        int q  = idx / nk;
        int kk = idx - q * nk;
        const float* qp = &sQ[q * KSTR];
        const float* kp = &sK[kk * KSTR];
        float acc = 0.f;
#pragma unroll
        for (int d = 0; d < HD; d++) acc = fmaf(qp[d], kp[d], acc);
        int i = q0 + q, j = kstart + kk;
        bool ok = (j <= i) && (j >= i - WIN);
        sS[q * SSTR + kk] = ok ? acc * scale : -1e30f;
    }
    __syncthreads();

    // Softmax: one warp handles 8 queries (lane-strided over keys)
    const int warp = tid >> 5, lane = tid & 31;
    for (int q = warp; q < QT; q += 8) {
        float* row = &sS[q * SSTR];
        float m = -1e30f;
        for (int kk = lane; kk < nk; kk += 32) m = fmaxf(m, row[kk]);
#pragma unroll
        for (int o = 16; o; o >>= 1) m = fmaxf(m, __shfl_xor_sync(0xffffffffu, m, o));
        float s = 0.f;
        for (int kk = lane; kk < nk; kk += 32) {
            float e = __expf(row[kk] - m);
            row[kk] = e;
            s += e;
        }
#pragma unroll
        for (int o = 16; o; o >>= 1) s += __shfl_xor_sync(0xffffffffu, s, o);
        float inv = 1.f / s;
        for (int kk = lane; kk < nk; kk += 32) row[kk] *= inv;
    }
    __syncthreads();

    // Out = P @ V ; write to [B*T, D] with head-interleaved layout = [B,T,H,HD]
    for (int idx = tid; idx < QT * HD; idx += 256) {
        int q = idx >> 6, d = idx & 63;
        const float* row = &sS[q * SSTR];
        float acc = 0.f;
        for (int kk = 0; kk < nk; kk++) acc = fmaf(row[kk], sV[kk * KSTR + d], acc);
        att[(long)(b * TT + q0 + q) * DD + hq + d] = acc;
    }
}

// ---------------------------------------------------------------------------
extern "C" void kernel_launch(void* const* d_in, const int* in_sizes, int n_in,
                              void* d_out, int out_size) {
    const float* x    = (const float*)d_in[0];   // [4,2048,768]
    const float* Wqkv = (const float*)d_in[1];   // [768,2304]
    const float* Wout = (const float*)d_in[2];   // [768,768]
    float* out = (float*)d_out;                  // [4,2048,768]

    float *qkv, *att;
    cudaGetSymbolAddress((void**)&qkv, g_qkv);
    cudaGetSymbolAddress((void**)&att, g_att);

    // Attention smem: (QT + 2*NKMAX)*KSTR + QT*SSTR floats
    const int smem_bytes = (int)(((QT + 2 * NKMAX) * KSTR + QT * SSTR) * sizeof(float)); // 165632
    cudaFuncSetAttribute(attn_kernel, cudaFuncAttributeMaxDynamicSharedMemorySize, smem_bytes);

    const int M = BB * TT;   // 8192

    // 1) QKV projection: [8192,768] x [768,2304]
    sgemm128<<<dim3((3 * DD) / 128, M / 128), 256>>>(x, Wqkv, qkv, M, 3 * DD, DD);

    // 2) Sliding-window attention
    attn_kernel<<<dim3(TT / QT, HH, BB), 256, smem_bytes>>>(qkv, att);

    // 3) Output projection: [8192,768] x [768,768]
    sgemm128<<<dim3(DD / 128, M / 128), 256>>>(att, Wout, out, M, DD, DD);
}

// round 5
// speedup vs baseline: 1.5547x; 1.5547x over previous
#include <cuda_runtime.h>
#include <cstdint>
#include <cstddef>

// ---------------- problem constants ----------------
#define BB 4
#define TT 2048
#define DD 768
#define HH 12
#define HD 64
#define WIN 128
#define QT 64
#define NKMAX 192
#define KSTR 65
#define SSTR 192

// ---------------- GEMM tiling ----------------
#define MT 128
#define NT 128
#define KC 32                 // K chunk (floats)
#define KDIM 768
#define NCHUNK (KDIM / KC)    // 24
#define GEMM_THREADS 256
#define STR 36                // smem row stride in floats (conflict-free fragments)
#define TILE_F (128 * STR)    // floats per tile buffer

// dynamic smem: [stage][A|B] tiles
#define GEMM_SMEM (2 * 2 * TILE_F * 4)   // 73728 bytes

// ---------------- device scratch ----------------
__device__ __align__(128) float g_qkv[(size_t)BB * TT * 3 * DD];
__device__ __align__(128) float g_att[(size_t)BB * TT * DD];
__device__ __align__(128) float g_wqkvT[(size_t)3 * DD * DD];   // [2304, 768]
__device__ __align__(128) float g_woutT[(size_t)DD * DD];       // [768, 768]

// ---------------- helpers ----------------
__device__ __forceinline__ uint32_t smem_u32(const void* p) {
    uint32_t a;
    asm("{ .reg .u64 t; cvta.to.shared.u64 t, %1; cvt.u32.u64 %0, t; }" : "=r"(a) : "l"(p));
    return a;
}
__device__ __forceinline__ void cpa16(uint32_t s, const void* g) {
    asm volatile("cp.async.cg.shared.global [%0], [%1], 16;" :: "r"(s), "l"(g));
}
__device__ __forceinline__ uint32_t f2tf32(float x) {
    uint32_t r;
    asm("cvt.rna.tf32.f32 %0, %1;" : "=r"(r) : "f"(x));
    return r;
}
__device__ __forceinline__ void mma_tf32_16x8x8(float* d, const uint32_t* a, const uint32_t* b) {
    asm volatile(
        "mma.sync.aligned.m16n8k8.row.col.f32.tf32.tf32.f32 "
        "{%0,%1,%2,%3}, {%4,%5,%6,%7}, {%8,%9}, {%0,%1,%2,%3};"
        : "+f"(d[0]), "+f"(d[1]), "+f"(d[2]), "+f"(d[3])
        : "r"(a[0]), "r"(a[1]), "r"(a[2]), "r"(a[3]), "r"(b[0]), "r"(b[1]));
}

// ---------------------------------------------------------------------------
// 32x32 tiled transpose: dst[c][r] = src[r][c].  src is [R, C], dst is [C, R].
// ---------------------------------------------------------------------------
__global__ void __launch_bounds__(256) transpose_k(const float* __restrict__ src,
                                                   float* __restrict__ dst,
                                                   int R, int C) {
    __shared__ float t[32][33];
    const int c0 = blockIdx.x * 32, r0 = blockIdx.y * 32;
    const int x = threadIdx.x, y = threadIdx.y;   // block (32, 8)
#pragma unroll
    for (int dy = 0; dy < 32; dy += 8)
        t[y + dy][x] = src[(size_t)(r0 + y + dy) * C + c0 + x];
    __syncthreads();
#pragma unroll
    for (int dy = 0; dy < 32; dy += 8)
        dst[(size_t)(c0 + y + dy) * R + r0 + x] = t[x][y + dy];
}

// ---------------------------------------------------------------------------
// tf32 mma.sync GEMM: C[M,N] = A[M,768] * Bt[N,768]^T   (Bt is K-major [N,K])
// CTA 128x128, K-chunk 32, cp.async double buffer, 8 warps (2M x 4N), warp
// tile 64x32 via m16n8k8 fragments.
// ---------------------------------------------------------------------------
__global__ void __launch_bounds__(GEMM_THREADS) gemm_tf32(const float* __restrict__ A,
                                                          const float* __restrict__ Bt,
                                                          float* __restrict__ C,
                                                          int N) {
    extern __shared__ float smf[];
    float* sA[2] = { smf,                smf + 2 * TILE_F };
    float* sB[2] = { smf + TILE_F,       smf + 3 * TILE_F };
    const uint32_t sAu[2] = { smem_u32(sA[0]), smem_u32(sA[1]) };
    const uint32_t sBu[2] = { smem_u32(sB[0]), smem_u32(sB[1]) };

    const int tid = threadIdx.x;
    const int wid = tid >> 5, lane = tid & 31;
    const int gid = lane >> 2, tg = lane & 3;     // groupID, threadID_in_group
    const int wm = (wid & 1) * 64;                // warp M offset in CTA tile
    const int wn = (wid >> 1) * 32;               // warp N offset
    const int bm = blockIdx.y * MT;
    const int bn = blockIdx.x * NT;

    // Per-thread loader slots: 4 float4 for A, 4 for B per chunk.
    int lrow[4], lc4[4];
    const float *gA[4], *gB[4];
#pragma unroll
    for (int i = 0; i < 4; i++) {
        int f = tid + i * 256;          // 0..1023
        lrow[i] = f >> 3;               // 0..127
        lc4[i]  = f & 7;                // 0..7 (float4 within 32-float row)
        gA[i] = A  + (size_t)(bm + lrow[i]) * KDIM + lc4[i] * 4;
        gB[i] = Bt + (size_t)(bn + lrow[i]) * KDIM + lc4[i] * 4;
    }

    auto load_chunk = [&](int kc, int s) {
        const int ko = kc * KC;
#pragma unroll
        for (int i = 0; i < 4; i++) {
            uint32_t off = (uint32_t)(lrow[i] * STR + lc4[i] * 4) * 4u;
            cpa16(sAu[s] + off, gA[i] + ko);
            cpa16(sBu[s] + off, gB[i] + ko);
        }
        asm volatile("cp.async.commit_group;" ::: "memory");
    };

    float acc[4][4][4];
#pragma unroll
    for (int mi = 0; mi < 4; mi++)
#pragma unroll
        for (int ni = 0; ni < 4; ni++)
#pragma unroll
            for (int q = 0; q < 4; q++) acc[mi][ni][q] = 0.f;

    load_chunk(0, 0);

    for (int c = 0; c < NCHUNK; ++c) {
        const int s = c & 1;
        if (c + 1 < NCHUNK) {
            load_chunk(c + 1, s ^ 1);
            asm volatile("cp.async.wait_group 1;" ::: "memory");
        } else {
            asm volatile("cp.async.wait_group 0;" ::: "memory");
        }
        __syncthreads();

        const float* cA = sA[s];
        const float* cB = sB[s];
#pragma unroll
        for (int k8 = 0; k8 < 4; k8++) {
            const int k0 = k8 * 8;
            uint32_t af[4][4], bf[4][2];
#pragma unroll
            for (int mi = 0; mi < 4; mi++) {
                const int r0 = wm + mi * 16 + gid;
                af[mi][0] = f2tf32(cA[(r0)     * STR + k0 + tg]);
                af[mi][1] = f2tf32(cA[(r0 + 8) * STR + k0 + tg]);
                af[mi][2] = f2tf32(cA[(r0)     * STR + k0 + tg + 4]);
                af[mi][3] = f2tf32(cA[(r0 + 8) * STR + k0 + tg + 4]);
            }
#pragma unroll
            for (int ni = 0; ni < 4; ni++) {
                const int n0 = wn + ni * 8 + gid;
                bf[ni][0] = f2tf32(cB[n0 * STR + k0 + tg]);
                bf[ni][1] = f2tf32(cB[n0 * STR + k0 + tg + 4]);
            }
#pragma unroll
            for (int mi = 0; mi < 4; mi++)
#pragma unroll
                for (int ni = 0; ni < 4; ni++)
                    mma_tf32_16x8x8(acc[mi][ni], af[mi], bf[ni]);
        }
        __syncthreads();
    }

    // Epilogue: c0/c1 at (row, 2*tg), c2/c3 at (row+8, 2*tg)
#pragma unroll
    for (int mi = 0; mi < 4; mi++) {
        const int r0 = bm + wm + mi * 16 + gid;
#pragma unroll
        for (int ni = 0; ni < 4; ni++) {
            const int c0 = bn + wn + ni * 8 + tg * 2;
            float2 v0 = make_float2(acc[mi][ni][0], acc[mi][ni][1]);
            float2 v1 = make_float2(acc[mi][ni][2], acc[mi][ni][3]);
            *reinterpret_cast<float2*>(&C[(size_t)r0 * N + c0])       = v0;
            *reinterpret_cast<float2*>(&C[(size_t)(r0 + 8) * N + c0]) = v1;
        }
    }
}

// ---------------------------------------------------------------------------
// Sliding-window attention (unchanged, proven at rel_err 3e-7)
// ---------------------------------------------------------------------------
__global__ void __launch_bounds__(256) attn_kernel(const float* __restrict__ qkv,
                                                   float* __restrict__ att) {
    const int q0 = blockIdx.x * QT;
    const int h  = blockIdx.y;
    const int b  = blockIdx.z;
    const int tid = threadIdx.x;

    extern __shared__ float sm[];
    float* sQ = sm;
    float* sK = sQ + QT * KSTR;
    float* sV = sK + NKMAX * KSTR;
    float* sS = sV + NKMAX * KSTR;

    const int kstart = max(0, q0 - WIN);
    const int kend   = q0 + QT;
    const int nk     = kend - kstart;
    const int hq = h * HD;

    for (int idx = tid; idx < QT * HD; idx += 256) {
        int q = idx >> 6, d = idx & 63;
        sQ[q * KSTR + d] = qkv[(size_t)(b * TT + q0 + q) * (3 * DD) + hq + d];
    }
    for (int idx = tid; idx < nk * HD; idx += 256) {
        int kk = idx >> 6, d = idx & 63;
        size_t r = (size_t)(b * TT + kstart + kk) * (3 * DD);
        sK[kk * KSTR + d] = qkv[r + DD + hq + d];
        sV[kk * KSTR + d] = qkv[r + 2 * DD + hq + d];
    }
    __syncthreads();

    const float scale = 0.125f;
    const int total = QT * nk;
    for (int idx = tid; idx < total; idx += 256) {
        int q  = idx / nk;
        int kk = idx - q * nk;
        const float* qp = &sQ[q * KSTR];
        const float* kp = &sK[kk * KSTR];
        float acc = 0.f;
#pragma unroll
        for (int d = 0; d < HD; d++) acc = fmaf(qp[d], kp[d], acc);
        int i = q0 + q, j = kstart + kk;
        bool ok = (j <= i) && (j >= i - WIN);
        sS[q * SSTR + kk] = ok ? acc * scale : -1e30f;
    }
    __syncthreads();

    const int warp = tid >> 5, lane = tid & 31;
    for (int q = warp; q < QT; q += 8) {
        float* row = &sS[q * SSTR];
        float m = -1e30f;
        for (int kk = lane; kk < nk; kk += 32) m = fmaxf(m, row[kk]);
#pragma unroll
        for (int o = 16; o; o >>= 1) m = fmaxf(m, __shfl_xor_sync(0xffffffffu, m, o));
        float s = 0.f;
        for (int kk = lane; kk < nk; kk += 32) {
            float e = __expf(row[kk] - m);
            row[kk] = e;
            s += e;
        }
#pragma unroll
        for (int o = 16; o; o >>= 1) s += __shfl_xor_sync(0xffffffffu, s, o);
        float inv = 1.f / s;
        for (int kk = lane; kk < nk; kk += 32) row[kk] *= inv;
    }
    __syncthreads();

    for (int idx = tid; idx < QT * HD; idx += 256) {
        int q = idx >> 6, d = idx & 63;
        const float* row = &sS[q * SSTR];
        float acc = 0.f;
        for (int kk = 0; kk < nk; kk++) acc = fmaf(row[kk], sV[kk * KSTR + d], acc);
        att[(size_t)(b * TT + q0 + q) * DD + hq + d] = acc;
    }
}

// ---------------------------------------------------------------------------
extern "C" void kernel_launch(void* const* d_in, const int* in_sizes, int n_in,
                              void* d_out, int out_size) {
    const float* x    = (const float*)d_in[0];   // [4,2048,768]
    const float* Wqkv = (const float*)d_in[1];   // [768,2304]
    const float* Wout = (const float*)d_in[2];   // [768,768]
    float* out = (float*)d_out;                  // [4,2048,768]

    float *qkv, *att, *wqkvT, *woutT;
    cudaGetSymbolAddress((void**)&qkv, g_qkv);
    cudaGetSymbolAddress((void**)&att, g_att);
    cudaGetSymbolAddress((void**)&wqkvT, g_wqkvT);
    cudaGetSymbolAddress((void**)&woutT, g_woutT);

    const int attn_smem = (int)(((QT + 2 * NKMAX) * KSTR + QT * SSTR) * sizeof(float));
    cudaFuncSetAttribute(attn_kernel, cudaFuncAttributeMaxDynamicSharedMemorySize, attn_smem);
    cudaFuncSetAttribute(gemm_tf32, cudaFuncAttributeMaxDynamicSharedMemorySize, GEMM_SMEM);

    const int M = BB * TT;   // 8192

    // 0) Transpose weights to K-major [N, K]
    transpose_k<<<dim3(3 * DD / 32, DD / 32), dim3(32, 8)>>>(Wqkv, wqkvT, DD, 3 * DD);
    transpose_k<<<dim3(DD / 32, DD / 32), dim3(32, 8)>>>(Wout, woutT, DD, DD);

    // 1) QKV projection (tf32 mma): [8192,768] x [768,2304]
    gemm_tf32<<<dim3(3 * DD / NT, M / MT), GEMM_THREADS, GEMM_SMEM>>>(x, wqkvT, qkv, 3 * DD);

    // 2) Sliding-window attention
    attn_kernel<<<dim3(TT / QT, HH, BB), 256, attn_smem>>>(qkv, att);

    // 3) Output projection (tf32 mma): [8192,768] x [768,768]
    gemm_tf32<<<dim3(DD / NT, M / MT), GEMM_THREADS, GEMM_SMEM>>>(att, woutT, out, DD);
}

// round 6
// speedup vs baseline: 3.2042x; 2.0610x over previous
#include <cuda_runtime.h>
#include <cstdint>
#include <cstddef>

// ---------------- problem constants ----------------
#define BB 4
#define TT 2048
#define DD 768
#define HH 12
#define HD 64
#define WIN 128
#define QT 64
#define NKM 192

// ---------------- GEMM tiling ----------------
#define MT 128
#define NT 128
#define KC 32
#define KDIM 768
#define NCHUNK (KDIM / KC)
#define GEMM_THREADS 256
#define STR 36
#define TILE_F (128 * STR)
#define GEMM_SMEM (2 * 2 * TILE_F * 4)

// ---------------- attention smem strides ----------------
#define ASTR 68     // Q/K row stride (68 % 32 == 4 -> conflict-free fragments)
#define VSTR 196    // Vt/S row stride (196 % 32 == 4)
#define ATT_F (QT * ASTR + NKM * ASTR + HD * VSTR + QT * VSTR)   // 42496 floats
#define ATT_SMEM (ATT_F * 4)                                     // 169984 B

// ---------------- device scratch ----------------
__device__ __align__(128) float g_qkv[(size_t)BB * TT * 3 * DD];
__device__ __align__(128) float g_att[(size_t)BB * TT * DD];
__device__ __align__(128) float g_wqkvT[(size_t)3 * DD * DD];
__device__ __align__(128) float g_woutT[(size_t)DD * DD];

// ---------------- helpers ----------------
__device__ __forceinline__ uint32_t smem_u32(const void* p) {
    uint32_t a;
    asm("{ .reg .u64 t; cvta.to.shared.u64 t, %1; cvt.u32.u64 %0, t; }" : "=r"(a) : "l"(p));
    return a;
}
__device__ __forceinline__ void cpa16(uint32_t s, const void* g) {
    asm volatile("cp.async.cg.shared.global [%0], [%1], 16;" :: "r"(s), "l"(g));
}
__device__ __forceinline__ uint32_t f2tf32(float x) {
    uint32_t r;
    asm("cvt.rna.tf32.f32 %0, %1;" : "=r"(r) : "f"(x));
    return r;
}
__device__ __forceinline__ void mma_tf32_16x8x8(float* d, const uint32_t* a, const uint32_t* b) {
    asm volatile(
        "mma.sync.aligned.m16n8k8.row.col.f32.tf32.tf32.f32 "
        "{%0,%1,%2,%3}, {%4,%5,%6,%7}, {%8,%9}, {%0,%1,%2,%3};"
        : "+f"(d[0]), "+f"(d[1]), "+f"(d[2]), "+f"(d[3])
        : "r"(a[0]), "r"(a[1]), "r"(a[2]), "r"(a[3]), "r"(b[0]), "r"(b[1]));
}

// ---------------------------------------------------------------------------
// 32x32 tiled transpose: dst[c][r] = src[r][c].
// ---------------------------------------------------------------------------
__global__ void __launch_bounds__(256) transpose_k(const float* __restrict__ src,
                                                   float* __restrict__ dst,
                                                   int R, int C) {
    __shared__ float t[32][33];
    const int c0 = blockIdx.x * 32, r0 = blockIdx.y * 32;
    const int x = threadIdx.x, y = threadIdx.y;
#pragma unroll
    for (int dy = 0; dy < 32; dy += 8)
        t[y + dy][x] = src[(size_t)(r0 + y + dy) * C + c0 + x];
    __syncthreads();
#pragma unroll
    for (int dy = 0; dy < 32; dy += 8)
        dst[(size_t)(c0 + y + dy) * R + r0 + x] = t[x][y + dy];
}

// ---------------------------------------------------------------------------
// tf32 mma.sync GEMM (unchanged from R5 passing kernel)
// ---------------------------------------------------------------------------
__global__ void __launch_bounds__(GEMM_THREADS) gemm_tf32(const float* __restrict__ A,
                                                          const float* __restrict__ Bt,
                                                          float* __restrict__ C,
                                                          int N) {
    extern __shared__ float smf[];
    float* sA[2] = { smf,          smf + 2 * TILE_F };
    float* sB[2] = { smf + TILE_F, smf + 3 * TILE_F };
    const uint32_t sAu[2] = { smem_u32(sA[0]), smem_u32(sA[1]) };
    const uint32_t sBu[2] = { smem_u32(sB[0]), smem_u32(sB[1]) };

    const int tid = threadIdx.x;
    const int wid = tid >> 5, lane = tid & 31;
    const int gid = lane >> 2, tg = lane & 3;
    const int wm = (wid & 1) * 64;
    const int wn = (wid >> 1) * 32;
    const int bm = blockIdx.y * MT;
    const int bn = blockIdx.x * NT;

    int lrow[4], lc4[4];
    const float *gA[4], *gB[4];
#pragma unroll
    for (int i = 0; i < 4; i++) {
        int f = tid + i * 256;
        lrow[i] = f >> 3;
        lc4[i]  = f & 7;
        gA[i] = A  + (size_t)(bm + lrow[i]) * KDIM + lc4[i] * 4;
        gB[i] = Bt + (size_t)(bn + lrow[i]) * KDIM + lc4[i] * 4;
    }

    auto load_chunk = [&](int kc, int s) {
        const int ko = kc * KC;
#pragma unroll
        for (int i = 0; i < 4; i++) {
            uint32_t off = (uint32_t)(lrow[i] * STR + lc4[i] * 4) * 4u;
            cpa16(sAu[s] + off, gA[i] + ko);
            cpa16(sBu[s] + off, gB[i] + ko);
        }
        asm volatile("cp.async.commit_group;" ::: "memory");
    };

    float acc[4][4][4];
#pragma unroll
    for (int mi = 0; mi < 4; mi++)
#pragma unroll
        for (int ni = 0; ni < 4; ni++)
#pragma unroll
            for (int q = 0; q < 4; q++) acc[mi][ni][q] = 0.f;

    load_chunk(0, 0);

    for (int c = 0; c < NCHUNK; ++c) {
        const int s = c & 1;
        if (c + 1 < NCHUNK) {
            load_chunk(c + 1, s ^ 1);
            asm volatile("cp.async.wait_group 1;" ::: "memory");
        } else {
            asm volatile("cp.async.wait_group 0;" ::: "memory");
        }
        __syncthreads();

        const float* cA = sA[s];
        const float* cB = sB[s];
#pragma unroll
        for (int k8 = 0; k8 < 4; k8++) {
            const int k0 = k8 * 8;
            uint32_t af[4][4], bf[4][2];
#pragma unroll
            for (int mi = 0; mi < 4; mi++) {
                const int r0 = wm + mi * 16 + gid;
                af[mi][0] = f2tf32(cA[(r0)     * STR + k0 + tg]);
                af[mi][1] = f2tf32(cA[(r0 + 8) * STR + k0 + tg]);
                af[mi][2] = f2tf32(cA[(r0)     * STR + k0 + tg + 4]);
                af[mi][3] = f2tf32(cA[(r0 + 8) * STR + k0 + tg + 4]);
            }
#pragma unroll
            for (int ni = 0; ni < 4; ni++) {
                const int n0 = wn + ni * 8 + gid;
                bf[ni][0] = f2tf32(cB[n0 * STR + k0 + tg]);
                bf[ni][1] = f2tf32(cB[n0 * STR + k0 + tg + 4]);
            }
#pragma unroll
            for (int mi = 0; mi < 4; mi++)
#pragma unroll
                for (int ni = 0; ni < 4; ni++)
                    mma_tf32_16x8x8(acc[mi][ni], af[mi], bf[ni]);
        }
        __syncthreads();
    }

#pragma unroll
    for (int mi = 0; mi < 4; mi++) {
        const int r0 = bm + wm + mi * 16 + gid;
#pragma unroll
        for (int ni = 0; ni < 4; ni++) {
            const int c0 = bn + wn + ni * 8 + tg * 2;
            float2 v0 = make_float2(acc[mi][ni][0], acc[mi][ni][1]);
            float2 v1 = make_float2(acc[mi][ni][2], acc[mi][ni][3]);
            *reinterpret_cast<float2*>(&C[(size_t)r0 * N + c0])       = v0;
            *reinterpret_cast<float2*>(&C[(size_t)(r0 + 8) * N + c0]) = v1;
        }
    }
}

// ---------------------------------------------------------------------------
// Tensorized sliding-window attention.
// CTA = (64-query tile, head, batch), 256 threads = 8 warps.
// Warp w: rows [((w>>1)*16, +16), N-half (w&1): 96 score cols / 32 out cols.
// ---------------------------------------------------------------------------
__global__ void __launch_bounds__(256) attn_mma(const float* __restrict__ qkv,
                                                float* __restrict__ att) {
    const int q0 = blockIdx.x * QT;
    const int h  = blockIdx.y;
    const int b  = blockIdx.z;
    const int tid = threadIdx.x;
    const int wid = tid >> 5, lane = tid & 31;
    const int gid = lane >> 2, tg = lane & 3;
    const int mrow  = (wid >> 1) * 16;     // warp's query-row base
    const int nhalf = (wid & 1);

    extern __shared__ float sm[];
    float* sQ  = sm;                        // [64][ASTR]
    float* sK  = sQ  + QT  * ASTR;          // [192][ASTR]
    float* sVt = sK  + NKM * ASTR;          // [64][VSTR]  (V transposed: [d][kk])
    float* sS  = sVt + HD  * VSTR;          // [64][VSTR]

    const int kstart = max(0, q0 - WIN);
    const int nk     = q0 + QT - kstart;    // 64 or 192
    const int hq     = h * HD;
    const size_t rowbase = (size_t)(b * TT) * (3 * DD);

    // ---- loads (float4 vectorized) ----
    for (int idx = tid; idx < QT * (HD / 4); idx += 256) {
        int q = idx >> 4, d4 = (idx & 15) * 4;
        float4 v = *reinterpret_cast<const float4*>(
            &qkv[rowbase + (size_t)(q0 + q) * (3 * DD) + hq + d4]);
        float* dst = &sQ[q * ASTR + d4];
        dst[0] = v.x; dst[1] = v.y; dst[2] = v.z; dst[3] = v.w;
    }
    for (int idx = tid; idx < nk * (HD / 4); idx += 256) {
        int kk = idx >> 4, d4 = (idx & 15) * 4;
        float4 v = *reinterpret_cast<const float4*>(
            &qkv[rowbase + (size_t)(kstart + kk) * (3 * DD) + DD + hq + d4]);
        float* dst = &sK[kk * ASTR + d4];
        dst[0] = v.x; dst[1] = v.y; dst[2] = v.z; dst[3] = v.w;
    }
    // Vt zero-fill (masked keys must contribute exactly 0, never 0*garbage)
    for (int idx = tid; idx < HD * VSTR; idx += 256) sVt[idx] = 0.f;
    __syncthreads();
    for (int idx = tid; idx < nk * (HD / 4); idx += 256) {
        int kk = idx >> 4, d4 = (idx & 15) * 4;
        float4 v = *reinterpret_cast<const float4*>(
            &qkv[rowbase + (size_t)(kstart + kk) * (3 * DD) + 2 * DD + hq + d4]);
        sVt[(d4 + 0) * VSTR + kk] = v.x;
        sVt[(d4 + 1) * VSTR + kk] = v.y;
        sVt[(d4 + 2) * VSTR + kk] = v.z;
        sVt[(d4 + 3) * VSTR + kk] = v.w;
    }
    __syncthreads();

    // ---- QK^T: warp computes 16 x 96 scores (12 n-frags x 8 k-steps) ----
    {
        float accS[12][4];
#pragma unroll
        for (int ni = 0; ni < 12; ni++)
#pragma unroll
            for (int q = 0; q < 4; q++) accS[ni][q] = 0.f;

        const int ncol0 = nhalf * 96;
        const int r0 = mrow + gid;
#pragma unroll
        for (int k8 = 0; k8 < 8; k8++) {
            const int k0 = k8 * 8;
            uint32_t af[4];
            af[0] = f2tf32(sQ[(r0)     * ASTR + k0 + tg]);
            af[1] = f2tf32(sQ[(r0 + 8) * ASTR + k0 + tg]);
            af[2] = f2tf32(sQ[(r0)     * ASTR + k0 + tg + 4]);
            af[3] = f2tf32(sQ[(r0 + 8) * ASTR + k0 + tg + 4]);
#pragma unroll
            for (int ni = 0; ni < 12; ni++) {
                const int n0 = ncol0 + ni * 8 + gid;
                uint32_t bf[2];
                bf[0] = f2tf32(sK[n0 * ASTR + k0 + tg]);
                bf[1] = f2tf32(sK[n0 * ASTR + k0 + tg + 4]);
                mma_tf32_16x8x8(accS[ni], af, bf);
            }
        }

        // masked store of scores (col >= nk is implied masked since j > i)
        const float scale = 0.125f;
#pragma unroll
        for (int ni = 0; ni < 12; ni++) {
            const int col = ncol0 + ni * 8 + 2 * tg;
            const int r   = mrow + gid;
            const int i0 = q0 + r, i1 = i0 + 8;
            const int j0 = kstart + col, j1 = j0 + 1;
            sS[(r)     * VSTR + col]     = (j0 <= i0 && j0 >= i0 - WIN) ? accS[ni][0] * scale : -1e30f;
            sS[(r)     * VSTR + col + 1] = (j1 <= i0 && j1 >= i0 - WIN) ? accS[ni][1] * scale : -1e30f;
            sS[(r + 8) * VSTR + col]     = (j0 <= i1 && j0 >= i1 - WIN) ? accS[ni][2] * scale : -1e30f;
            sS[(r + 8) * VSTR + col + 1] = (j1 <= i1 && j1 >= i1 - WIN) ? accS[ni][3] * scale : -1e30f;
        }
    }
    __syncthreads();

    // ---- softmax: warp per 8 rows, 192 fixed cols ----
    for (int q = wid; q < QT; q += 8) {
        float* row = &sS[q * VSTR];
        float m = -1e30f;
#pragma unroll
        for (int kk = lane; kk < NKM; kk += 32) m = fmaxf(m, row[kk]);
#pragma unroll
        for (int o = 16; o; o >>= 1) m = fmaxf(m, __shfl_xor_sync(0xffffffffu, m, o));
        float s = 0.f;
#pragma unroll
        for (int kk = lane; kk < NKM; kk += 32) {
            float e = __expf(row[kk] - m);
            row[kk] = e;
            s += e;
        }
#pragma unroll
        for (int o = 16; o; o >>= 1) s += __shfl_xor_sync(0xffffffffu, s, o);
        float inv = 1.f / s;
#pragma unroll
        for (int kk = lane; kk < NKM; kk += 32) row[kk] *= inv;
    }
    __syncthreads();

    // ---- PV: warp computes 16 x 32 output (4 n-frags x 24 k-steps) ----
    {
        float accO[4][4];
#pragma unroll
        for (int ni = 0; ni < 4; ni++)
#pragma unroll
            for (int q = 0; q < 4; q++) accO[ni][q] = 0.f;

        const int dcol0 = nhalf * 32;
        const int r0 = mrow + gid;
#pragma unroll
        for (int ks = 0; ks < 24; ks++) {
            const int k0 = ks * 8;
            uint32_t af[4];
            af[0] = f2tf32(sS[(r0)     * VSTR + k0 + tg]);
            af[1] = f2tf32(sS[(r0 + 8) * VSTR + k0 + tg]);
            af[2] = f2tf32(sS[(r0)     * VSTR + k0 + tg + 4]);
            af[3] = f2tf32(sS[(r0 + 8) * VSTR + k0 + tg + 4]);
#pragma unroll
            for (int ni = 0; ni < 4; ni++) {
                const int n0 = dcol0 + ni * 8 + gid;
                uint32_t bf[2];
                bf[0] = f2tf32(sVt[n0 * VSTR + k0 + tg]);
                bf[1] = f2tf32(sVt[n0 * VSTR + k0 + tg + 4]);
                mma_tf32_16x8x8(accO[ni], af, bf);
            }
        }

#pragma unroll
        for (int ni = 0; ni < 4; ni++) {
            const int dc = dcol0 + ni * 8 + 2 * tg;
            const int r  = mrow + gid;
            float2 v0 = make_float2(accO[ni][0], accO[ni][1]);
            float2 v1 = make_float2(accO[ni][2], accO[ni][3]);
            *reinterpret_cast<float2*>(&att[(size_t)(b * TT + q0 + r)     * DD + hq + dc]) = v0;
            *reinterpret_cast<float2*>(&att[(size_t)(b * TT + q0 + r + 8) * DD + hq + dc]) = v1;
        }
    }
}

// ---------------------------------------------------------------------------
extern "C" void kernel_launch(void* const* d_in, const int* in_sizes, int n_in,
                              void* d_out, int out_size) {
    const float* x    = (const float*)d_in[0];
    const float* Wqkv = (const float*)d_in[1];
    const float* Wout = (const float*)d_in[2];
    float* out = (float*)d_out;

    float *qkv, *att, *wqkvT, *woutT;
    cudaGetSymbolAddress((void**)&qkv, g_qkv);
    cudaGetSymbolAddress((void**)&att, g_att);
    cudaGetSymbolAddress((void**)&wqkvT, g_wqkvT);
    cudaGetSymbolAddress((void**)&woutT, g_woutT);

    cudaFuncSetAttribute(attn_mma, cudaFuncAttributeMaxDynamicSharedMemorySize, ATT_SMEM);
    cudaFuncSetAttribute(gemm_tf32, cudaFuncAttributeMaxDynamicSharedMemorySize, GEMM_SMEM);

    const int M = BB * TT;

    transpose_k<<<dim3(3 * DD / 32, DD / 32), dim3(32, 8)>>>(Wqkv, wqkvT, DD, 3 * DD);
    transpose_k<<<dim3(DD / 32, DD / 32), dim3(32, 8)>>>(Wout, woutT, DD, DD);

    gemm_tf32<<<dim3(3 * DD / NT, M / MT), GEMM_THREADS, GEMM_SMEM>>>(x, wqkvT, qkv, 3 * DD);

    attn_mma<<<dim3(TT / QT, HH, BB), 256, ATT_SMEM>>>(qkv, att);

    gemm_tf32<<<dim3(DD / NT, M / MT), GEMM_THREADS, GEMM_SMEM>>>(att, woutT, out, DD);
}

// round 7
// speedup vs baseline: 3.4654x; 1.0815x over previous
#include <cuda_runtime.h>
#include <cstdint>
#include <cstddef>

// ---------------- problem constants ----------------
#define BB 4
#define TT 2048
#define DD 768
#define HH 12
#define HD 64
#define WIN 128
#define QT 64
#define NKM 192

// ---------------- GEMM tiling ----------------
#define MT 128
#define NT 128
#define KC 32
#define KDIM 768
#define NCHUNK (KDIM / KC)
#define GEMM_THREADS 256
#define STR 36
#define TILE_F (128 * STR)
#define GEMM_SMEM (2 * 2 * TILE_F * 4)

// ---------------- attention smem strides ----------------
#define ASTR 68     // Q/K row stride (68 % 32 == 4 -> conflict-free fragments)
#define VSTR 196    // Vt/S row stride (196 % 32 == 4)
#define ATT_F (QT * ASTR + NKM * ASTR + HD * VSTR + QT * VSTR)
#define ATT_SMEM (ATT_F * 4)

// ---------------- device scratch ----------------
__device__ __align__(128) float g_x  [(size_t)BB * TT * DD];        // tf32-rounded x
__device__ __align__(128) float g_qkv[(size_t)BB * TT * 3 * DD];
__device__ __align__(128) float g_att[(size_t)BB * TT * DD];
__device__ __align__(128) float g_wqkvT[(size_t)3 * DD * DD];
__device__ __align__(128) float g_woutT[(size_t)DD * DD];

// ---------------- helpers ----------------
__device__ __forceinline__ uint32_t smem_u32(const void* p) {
    uint32_t a;
    asm("{ .reg .u64 t; cvta.to.shared.u64 t, %1; cvt.u32.u64 %0, t; }" : "=r"(a) : "l"(p));
    return a;
}
__device__ __forceinline__ void cpa16(uint32_t s, const void* g) {
    asm volatile("cp.async.cg.shared.global [%0], [%1], 16;" :: "r"(s), "l"(g));
}
__device__ __forceinline__ uint32_t f2tf32(float x) {
    uint32_t r;
    asm("cvt.rna.tf32.f32 %0, %1;" : "=r"(r) : "f"(x));
    return r;
}
__device__ __forceinline__ float rnd_tf32(float x) { return __uint_as_float(f2tf32(x)); }

__device__ __forceinline__ void mma_tf32_16x8x8(float* d, const uint32_t* a, const uint32_t* b) {
    asm volatile(
        "mma.sync.aligned.m16n8k8.row.col.f32.tf32.tf32.f32 "
        "{%0,%1,%2,%3}, {%4,%5,%6,%7}, {%8,%9}, {%0,%1,%2,%3};"
        : "+f"(d[0]), "+f"(d[1]), "+f"(d[2]), "+f"(d[3])
        : "r"(a[0]), "r"(a[1]), "r"(a[2]), "r"(a[3]), "r"(b[0]), "r"(b[1]));
}

// ---------------------------------------------------------------------------
// Elementwise tf32 round (x -> g_x), float4 vectorized.  n % 4 == 0.
// ---------------------------------------------------------------------------
__global__ void __launch_bounds__(256) round_tf32_k(const float* __restrict__ src,
                                                    float* __restrict__ dst, int n4) {
    int i = blockIdx.x * 256 + threadIdx.x;
    if (i < n4) {
        float4 v = reinterpret_cast<const float4*>(src)[i];
        v.x = rnd_tf32(v.x); v.y = rnd_tf32(v.y);
        v.z = rnd_tf32(v.z); v.w = rnd_tf32(v.w);
        reinterpret_cast<float4*>(dst)[i] = v;
    }
}

// ---------------------------------------------------------------------------
// 32x32 tiled transpose with tf32 rounding (weights only).
// ---------------------------------------------------------------------------
__global__ void __launch_bounds__(256) transpose_k(const float* __restrict__ src,
                                                   float* __restrict__ dst,
                                                   int R, int C) {
    __shared__ float t[32][33];
    const int c0 = blockIdx.x * 32, r0 = blockIdx.y * 32;
    const int x = threadIdx.x, y = threadIdx.y;
#pragma unroll
    for (int dy = 0; dy < 32; dy += 8)
        t[y + dy][x] = rnd_tf32(src[(size_t)(r0 + y + dy) * C + c0 + x]);
    __syncthreads();
#pragma unroll
    for (int dy = 0; dy < 32; dy += 8)
        dst[(size_t)(c0 + y + dy) * R + r0 + x] = t[x][y + dy];
}

// ---------------------------------------------------------------------------
// tf32 mma.sync GEMM; inputs are PRE-ROUNDED to tf32 (raw-bit fragment loads).
// round_out: round C to tf32 (for intermediates feeding further tf32 mma).
// ---------------------------------------------------------------------------
__global__ void __launch_bounds__(GEMM_THREADS, 2) gemm_tf32(const float* __restrict__ A,
                                                             const float* __restrict__ Bt,
                                                             float* __restrict__ C,
                                                             int N, int round_out) {
    extern __shared__ float smf[];
    float* sA[2] = { smf,          smf + 2 * TILE_F };
    float* sB[2] = { smf + TILE_F, smf + 3 * TILE_F };
    const uint32_t sAu[2] = { smem_u32(sA[0]), smem_u32(sA[1]) };
    const uint32_t sBu[2] = { smem_u32(sB[0]), smem_u32(sB[1]) };

    const int tid = threadIdx.x;
    const int wid = tid >> 5, lane = tid & 31;
    const int gid = lane >> 2, tg = lane & 3;
    const int wm = (wid & 1) * 64;
    const int wn = (wid >> 1) * 32;
    const int bm = blockIdx.y * MT;
    const int bn = blockIdx.x * NT;

    int lrow[4], lc4[4];
    const float *gA[4], *gB[4];
#pragma unroll
    for (int i = 0; i < 4; i++) {
        int f = tid + i * 256;
        lrow[i] = f >> 3;
        lc4[i]  = f & 7;
        gA[i] = A  + (size_t)(bm + lrow[i]) * KDIM + lc4[i] * 4;
        gB[i] = Bt + (size_t)(bn + lrow[i]) * KDIM + lc4[i] * 4;
    }

    auto load_chunk = [&](int kc, int s) {
        const int ko = kc * KC;
#pragma unroll
        for (int i = 0; i < 4; i++) {
            uint32_t off = (uint32_t)(lrow[i] * STR + lc4[i] * 4) * 4u;
            cpa16(sAu[s] + off, gA[i] + ko);
            cpa16(sBu[s] + off, gB[i] + ko);
        }
        asm volatile("cp.async.commit_group;" ::: "memory");
    };

    float acc[4][4][4];
#pragma unroll
    for (int mi = 0; mi < 4; mi++)
#pragma unroll
        for (int ni = 0; ni < 4; ni++)
#pragma unroll
            for (int q = 0; q < 4; q++) acc[mi][ni][q] = 0.f;

    load_chunk(0, 0);

    for (int c = 0; c < NCHUNK; ++c) {
        const int s = c & 1;
        if (c + 1 < NCHUNK) {
            load_chunk(c + 1, s ^ 1);
            asm volatile("cp.async.wait_group 1;" ::: "memory");
        } else {
            asm volatile("cp.async.wait_group 0;" ::: "memory");
        }
        __syncthreads();

        const uint32_t* cA = reinterpret_cast<const uint32_t*>(sA[s]);
        const uint32_t* cB = reinterpret_cast<const uint32_t*>(sB[s]);
#pragma unroll
        for (int k8 = 0; k8 < 4; k8++) {
            const int k0 = k8 * 8;
            uint32_t af[4][4], bf[4][2];
#pragma unroll
            for (int mi = 0; mi < 4; mi++) {
                const int r0 = wm + mi * 16 + gid;
                af[mi][0] = cA[(r0)     * STR + k0 + tg];
                af[mi][1] = cA[(r0 + 8) * STR + k0 + tg];
                af[mi][2] = cA[(r0)     * STR + k0 + tg + 4];
                af[mi][3] = cA[(r0 + 8) * STR + k0 + tg + 4];
            }
#pragma unroll
            for (int ni = 0; ni < 4; ni++) {
                const int n0 = wn + ni * 8 + gid;
                bf[ni][0] = cB[n0 * STR + k0 + tg];
                bf[ni][1] = cB[n0 * STR + k0 + tg + 4];
            }
#pragma unroll
            for (int mi = 0; mi < 4; mi++)
#pragma unroll
                for (int ni = 0; ni < 4; ni++)
                    mma_tf32_16x8x8(acc[mi][ni], af[mi], bf[ni]);
        }
        __syncthreads();
    }

#pragma unroll
    for (int mi = 0; mi < 4; mi++) {
        const int r0 = bm + wm + mi * 16 + gid;
#pragma unroll
        for (int ni = 0; ni < 4; ni++) {
            const int c0 = bn + wn + ni * 8 + tg * 2;
            float4 v = make_float4(acc[mi][ni][0], acc[mi][ni][1],
                                   acc[mi][ni][2], acc[mi][ni][3]);
            if (round_out) {
                v.x = rnd_tf32(v.x); v.y = rnd_tf32(v.y);
                v.z = rnd_tf32(v.z); v.w = rnd_tf32(v.w);
            }
            *reinterpret_cast<float2*>(&C[(size_t)r0 * N + c0])       = make_float2(v.x, v.y);
            *reinterpret_cast<float2*>(&C[(size_t)(r0 + 8) * N + c0]) = make_float2(v.z, v.w);
        }
    }
}

// ---------------------------------------------------------------------------
// Tensorized sliding-window attention (inputs pre-rounded; raw-bit fragments).
// ---------------------------------------------------------------------------
__global__ void __launch_bounds__(256) attn_mma(const float* __restrict__ qkv,
                                                float* __restrict__ att) {
    const int q0 = blockIdx.x * QT;
    const int h  = blockIdx.y;
    const int b  = blockIdx.z;
    const int tid = threadIdx.x;
    const int wid = tid >> 5, lane = tid & 31;
    const int gid = lane >> 2, tg = lane & 3;
    const int mrow  = (wid >> 1) * 16;
    const int nhalf = (wid & 1);

    extern __shared__ float sm[];
    float* sQ  = sm;                        // [64][ASTR]
    float* sK  = sQ  + QT  * ASTR;          // [192][ASTR]
    float* sVt = sK  + NKM * ASTR;          // [64][VSTR]
    float* sS  = sVt + HD  * VSTR;          // [64][VSTR]

    const int kstart = max(0, q0 - WIN);
    const int nk     = q0 + QT - kstart;
    const int hq     = h * HD;
    const size_t rowbase = (size_t)(b * TT) * (3 * DD);

    for (int idx = tid; idx < QT * (HD / 4); idx += 256) {
        int q = idx >> 4, d4 = (idx & 15) * 4;
        float4 v = *reinterpret_cast<const float4*>(
            &qkv[rowbase + (size_t)(q0 + q) * (3 * DD) + hq + d4]);
        float* dst = &sQ[q * ASTR + d4];
        dst[0] = v.x; dst[1] = v.y; dst[2] = v.z; dst[3] = v.w;
    }
    for (int idx = tid; idx < nk * (HD / 4); idx += 256) {
        int kk = idx >> 4, d4 = (idx & 15) * 4;
        float4 v = *reinterpret_cast<const float4*>(
            &qkv[rowbase + (size_t)(kstart + kk) * (3 * DD) + DD + hq + d4]);
        float* dst = &sK[kk * ASTR + d4];
        dst[0] = v.x; dst[1] = v.y; dst[2] = v.z; dst[3] = v.w;
    }
    for (int idx = tid; idx < HD * VSTR; idx += 256) sVt[idx] = 0.f;
    __syncthreads();
    for (int idx = tid; idx < nk * (HD / 4); idx += 256) {
        int kk = idx >> 4, d4 = (idx & 15) * 4;
        float4 v = *reinterpret_cast<const float4*>(
            &qkv[rowbase + (size_t)(kstart + kk) * (3 * DD) + 2 * DD + hq + d4]);
        sVt[(d4 + 0) * VSTR + kk] = v.x;
        sVt[(d4 + 1) * VSTR + kk] = v.y;
        sVt[(d4 + 2) * VSTR + kk] = v.z;
        sVt[(d4 + 3) * VSTR + kk] = v.w;
    }
    __syncthreads();

    // ---- QK^T ----
    {
        float accS[12][4];
#pragma unroll
        for (int ni = 0; ni < 12; ni++)
#pragma unroll
            for (int q = 0; q < 4; q++) accS[ni][q] = 0.f;

        const int ncol0 = nhalf * 96;
        const int r0 = mrow + gid;
        const uint32_t* uQ = reinterpret_cast<const uint32_t*>(sQ);
        const uint32_t* uK = reinterpret_cast<const uint32_t*>(sK);
#pragma unroll
        for (int k8 = 0; k8 < 8; k8++) {
            const int k0 = k8 * 8;
            uint32_t af[4];
            af[0] = uQ[(r0)     * ASTR + k0 + tg];
            af[1] = uQ[(r0 + 8) * ASTR + k0 + tg];
            af[2] = uQ[(r0)     * ASTR + k0 + tg + 4];
            af[3] = uQ[(r0 + 8) * ASTR + k0 + tg + 4];
#pragma unroll
            for (int ni = 0; ni < 12; ni++) {
                const int n0 = ncol0 + ni * 8 + gid;
                uint32_t bf[2];
                bf[0] = uK[n0 * ASTR + k0 + tg];
                bf[1] = uK[n0 * ASTR + k0 + tg + 4];
                mma_tf32_16x8x8(accS[ni], af, bf);
            }
        }

        const float scale = 0.125f;
#pragma unroll
        for (int ni = 0; ni < 12; ni++) {
            const int col = ncol0 + ni * 8 + 2 * tg;
            const int r   = mrow + gid;
            const int i0 = q0 + r, i1 = i0 + 8;
            const int j0 = kstart + col, j1 = j0 + 1;
            sS[(r)     * VSTR + col]     = (j0 <= i0 && j0 >= i0 - WIN) ? accS[ni][0] * scale : -1e30f;
            sS[(r)     * VSTR + col + 1] = (j1 <= i0 && j1 >= i0 - WIN) ? accS[ni][1] * scale : -1e30f;
            sS[(r + 8) * VSTR + col]     = (j0 <= i1 && j0 >= i1 - WIN) ? accS[ni][2] * scale : -1e30f;
            sS[(r + 8) * VSTR + col + 1] = (j1 <= i1 && j1 >= i1 - WIN) ? accS[ni][3] * scale : -1e30f;
        }
    }
    __syncthreads();

    // ---- softmax (rounded tf32 probabilities on write) ----
    for (int q = wid; q < QT; q += 8) {
        float* row = &sS[q * VSTR];
        float m = -1e30f;
#pragma unroll
        for (int kk = lane; kk < NKM; kk += 32) m = fmaxf(m, row[kk]);
#pragma unroll
        for (int o = 16; o; o >>= 1) m = fmaxf(m, __shfl_xor_sync(0xffffffffu, m, o));
        float s = 0.f;
        float ev[6];
#pragma unroll
        for (int t = 0; t < 6; t++) {
            float e = __expf(row[lane + t * 32] - m);
            ev[t] = e;
            s += e;
        }
#pragma unroll
        for (int o = 16; o; o >>= 1) s += __shfl_xor_sync(0xffffffffu, s, o);
        float inv = 1.f / s;
#pragma unroll
        for (int t = 0; t < 6; t++) row[lane + t * 32] = rnd_tf32(ev[t] * inv);
    }
    __syncthreads();

    // ---- PV ----
    {
        float accO[4][4];
#pragma unroll
        for (int ni = 0; ni < 4; ni++)
#pragma unroll
            for (int q = 0; q < 4; q++) accO[ni][q] = 0.f;

        const int dcol0 = nhalf * 32;
        const int r0 = mrow + gid;
        const uint32_t* uS = reinterpret_cast<const uint32_t*>(sS);
        const uint32_t* uV = reinterpret_cast<const uint32_t*>(sVt);
#pragma unroll
        for (int ks = 0; ks < 24; ks++) {
            const int k0 = ks * 8;
            uint32_t af[4];
            af[0] = uS[(r0)     * VSTR + k0 + tg];
            af[1] = uS[(r0 + 8) * VSTR + k0 + tg];
            af[2] = uS[(r0)     * VSTR + k0 + tg + 4];
            af[3] = uS[(r0 + 8) * VSTR + k0 + tg + 4];
#pragma unroll
            for (int ni = 0; ni < 4; ni++) {
                const int n0 = dcol0 + ni * 8 + gid;
                uint32_t bf[2];
                bf[0] = uV[n0 * VSTR + k0 + tg];
                bf[1] = uV[n0 * VSTR + k0 + tg + 4];
                mma_tf32_16x8x8(accO[ni], af, bf);
            }
        }

#pragma unroll
        for (int ni = 0; ni < 4; ni++) {
            const int dc = dcol0 + ni * 8 + 2 * tg;
            const int r  = mrow + gid;
            float2 v0 = make_float2(rnd_tf32(accO[ni][0]), rnd_tf32(accO[ni][1]));
            float2 v1 = make_float2(rnd_tf32(accO[ni][2]), rnd_tf32(accO[ni][3]));
            *reinterpret_cast<float2*>(&att[(size_t)(b * TT + q0 + r)     * DD + hq + dc]) = v0;
            *reinterpret_cast<float2*>(&att[(size_t)(b * TT + q0 + r + 8) * DD + hq + dc]) = v1;
        }
    }
}

// ---------------------------------------------------------------------------
extern "C" void kernel_launch(void* const* d_in, const int* in_sizes, int n_in,
                              void* d_out, int out_size) {
    const float* x    = (const float*)d_in[0];
    const float* Wqkv = (const float*)d_in[1];
    const float* Wout = (const float*)d_in[2];
    float* out = (float*)d_out;

    float *xr, *qkv, *att, *wqkvT, *woutT;
    cudaGetSymbolAddress((void**)&xr, g_x);
    cudaGetSymbolAddress((void**)&qkv, g_qkv);
    cudaGetSymbolAddress((void**)&att, g_att);
    cudaGetSymbolAddress((void**)&wqkvT, g_wqkvT);
    cudaGetSymbolAddress((void**)&woutT, g_woutT);

    cudaFuncSetAttribute(attn_mma, cudaFuncAttributeMaxDynamicSharedMemorySize, ATT_SMEM);
    cudaFuncSetAttribute(gemm_tf32, cudaFuncAttributeMaxDynamicSharedMemorySize, GEMM_SMEM);

    const int M = BB * TT;
    const int xn4 = M * DD / 4;

    // 0) tf32-round x; transpose+round weights
    round_tf32_k<<<(xn4 + 255) / 256, 256>>>(x, xr, xn4);
    transpose_k<<<dim3(3 * DD / 32, DD / 32), dim3(32, 8)>>>(Wqkv, wqkvT, DD, 3 * DD);
    transpose_k<<<dim3(DD / 32, DD / 32), dim3(32, 8)>>>(Wout, woutT, DD, DD);

    // 1) QKV projection (round output -> feeds tf32 attention)
    gemm_tf32<<<dim3(3 * DD / NT, M / MT), GEMM_THREADS, GEMM_SMEM>>>(xr, wqkvT, qkv, 3 * DD, 1);

    // 2) attention (rounds its own output)
    attn_mma<<<dim3(TT / QT, HH, BB), 256, ATT_SMEM>>>(qkv, att);

    // 3) output projection (no rounding of final result)
    gemm_tf32<<<dim3(DD / NT, M / MT), GEMM_THREADS, GEMM_SMEM>>>(att, woutT, out, DD, 0);
}